// round 16
// baseline (speedup 1.0000x reference)
#include <cuda_runtime.h>
#include <cuda_fp16.h>
#include <float.h>
#include <stdint.h>

// ---------------- problem constants ----------------
#define BATCH      8
#define NPTS       1024
#define NPOINTS    (BATCH * NPTS)        // 8192
#define HEADC      8
#define SHAPEC     256
#define XCH        (HEADC + SHAPEC)      // 264
#define NEXPERT    16
#define SC_HID     256
#define SC_OUT     128
#define K0PAD      160                   // 136 padded to 160
#define C1OUT      256
#define C2OUT      512
#define C3OUT      1024
#define DEC1       1024
#define DEC2       2048
#define DEC3       8192
#define ETILE      64
#define MAXTILES   (NPOINTS / ETILE + NEXPERT)   // 144
#define NPART      8                     // pool partials per batch (1024/128)

typedef __half h16;

// ---------------- scratch (device globals; no runtime alloc) ----------------
__device__ __align__(256) h16 g_xhi[NPOINTS * SHAPEC];
__device__ __align__(256) h16 g_a0hi[NPOINTS * K0PAD];
__device__ __align__(256) h16 g_a1hi[NPOINTS * C1OUT];
__device__ __align__(256) h16 g_a2hi[NPOINTS * C2OUT];
__device__ __align__(256) h16 g_w1hi[C1OUT * K0PAD];
__device__ __align__(256) h16 g_w2hi[C2OUT * C1OUT];
__device__ __align__(256) h16 g_w3hi[C3OUT * C2OUT];
__device__ __align__(256) h16 g_e1hi[NEXPERT * SC_HID * SHAPEC];
__device__ __align__(256) h16 g_e2hi[NEXPERT * SC_OUT * SC_HID];
__device__ float g_part[BATCH * NPART * C3OUT];
__device__ float g_d1[BATCH * DEC1];
__device__ float g_d2[BATCH * DEC2];
__device__ int   g_idx[NPOINTS];
__device__ int   g_tileExpert[MAXTILES];
__device__ int   g_tileStart[MAXTILES];
__device__ int   g_tileLen[MAXTILES];
__device__ int   g_nTiles;

// ---------------- ptx helpers (sm_80-safe) ----------------
__device__ __forceinline__ uint32_t smem_u32(const void* p) {
    uint32_t a;
    asm("{ .reg .u64 t; cvta.to.shared.u64 t, %1; cvt.u32.u64 %0, t; }" : "=r"(a) : "l"(p));
    return a;
}
#define CP_ASYNC16(dst, src) \
    asm volatile("cp.async.cg.shared.global [%0], [%1], 16;" :: "r"(dst), "l"(src))
#define CP_COMMIT() asm volatile("cp.async.commit_group;" ::: "memory")
#define CP_WAIT0()  asm volatile("cp.async.wait_group 0;" ::: "memory")
#define CP_WAIT1()  asm volatile("cp.async.wait_group 1;" ::: "memory")

#define LDSM4(r, addr) \
    asm volatile("ldmatrix.sync.aligned.m8n8.x4.shared.b16 {%0,%1,%2,%3}, [%4];" \
        : "=r"((r)[0]), "=r"((r)[1]), "=r"((r)[2]), "=r"((r)[3]) : "r"(addr))

__device__ __forceinline__ void mma_f32(float* d, const uint32_t* a,
                                        uint32_t b0, uint32_t b1) {
    asm volatile(
        "mma.sync.aligned.m16n8k16.row.col.f32.f16.f16.f32 "
        "{%0,%1,%2,%3}, {%4,%5,%6,%7}, {%8,%9}, {%0,%1,%2,%3};"
        : "+f"(d[0]), "+f"(d[1]), "+f"(d[2]), "+f"(d[3])
        : "r"(a[0]), "r"(a[1]), "r"(a[2]), "r"(a[3]), "r"(b0), "r"(b1));
}

__device__ __forceinline__ uint32_t pack2h(h16 a, h16 b) {
    __half2 t; t.x = a; t.y = b;
    return *(uint32_t*)&t;
}

// ---------------- 1. fused prep: transpose | tsplit | head | wconv | build --
#define PREP_T1 2048
#define PREP_T2 3584
#define PREP_T3 4608
#define WS_NB1 40
#define WS_NB2 128
#define WS_NB3 512
#define PREP_T4 (PREP_T3 + WS_NB1 + WS_NB2 + WS_NB3)   // 5288
#define PREP_NB (PREP_T4 + 1)                           // +1 build block

__global__ void __launch_bounds__(256) k_prep(
    const float* __restrict__ x, const int* __restrict__ cats,
    const float* __restrict__ W1, const float* __restrict__ W2,
    const float* __restrict__ Wc1, const float* __restrict__ Wc2,
    const float* __restrict__ Wc3)
{
    int bi = blockIdx.x;
    int tid = threadIdx.x;

    if (bi == PREP_T4) {
        // ---- counting sort by category (warp-aggregated atomics) ----
        __shared__ int cnt[NEXPERT];
        __shared__ int off[NEXPERT + 1];
        __shared__ int cur[NEXPERT];
        int lane = tid & 31;
        if (tid < NEXPERT) cnt[tid] = 0;
        __syncthreads();
        for (int i = tid; i < NPOINTS; i += 256) {
            int c = cats[i];
            unsigned m = __match_any_sync(0xFFFFFFFFu, c);
            int leader = __ffs(m) - 1;
            if (lane == leader) atomicAdd(&cnt[c], __popc(m));
        }
        __syncthreads();
        if (tid == 0) {
            int s = 0;
            for (int e = 0; e < NEXPERT; e++) { off[e] = s; s += cnt[e]; }
            off[NEXPERT] = s;
            int t = 0;
            for (int e = 0; e < NEXPERT; e++)
                for (int st = off[e]; st < off[e + 1]; st += ETILE) {
                    g_tileExpert[t] = e;
                    g_tileStart[t]  = st;
                    g_tileLen[t]    = min(ETILE, off[e + 1] - st);
                    t++;
                }
            g_nTiles = t;
        }
        __syncthreads();
        if (tid < NEXPERT) cur[tid] = off[tid];
        __syncthreads();
        for (int i = tid; i < NPOINTS; i += 256) {
            int c = cats[i];
            unsigned m = __match_any_sync(0xFFFFFFFFu, c);
            int leader = __ffs(m) - 1;
            int rank = __popc(m & ((1u << lane) - 1u));
            int base = 0;
            if (lane == leader) base = atomicAdd(&cur[c], __popc(m));
            base = __shfl_sync(m, base, leader);
            g_idx[base + rank] = i;
        }
        return;
    }

    __shared__ float t[32][33];
    int tx = tid & 31, ty = tid >> 5;

    if (bi < PREP_T1) {
        // ---- transpose x shape feats -> g_xhi ----
        int idx = bi;
        int cB = (idx & 7) * 32;
        int nB = ((idx >> 3) & 31) * 32;
        int b  = idx >> 8;
        const float* xb = x + (size_t)b * XCH * NPTS;
#pragma unroll
        for (int i = ty; i < 32; i += 8)
            t[i][tx] = xb[(size_t)(HEADC + cB + i) * NPTS + nB + tx];
        __syncthreads();
        size_t base = ((size_t)b * NPTS + nB) * SHAPEC + cB;
#pragma unroll
        for (int i = ty; i < 32; i += 8)
            g_xhi[base + (size_t)i * SHAPEC + tx] = __float2half_rn(t[tx][i]);
    } else if (bi < PREP_T2) {
        // ---- expert weight transpose (hi only) ----
        int r = bi - PREP_T1;
        const float* src; h16 *hi; int K, OUT, e, k0, o0;
        if (r < 1024) {
            e = r >> 6; int q = r & 63;
            k0 = (q & 7) * 32; o0 = (q >> 3) * 32;
            src = W1; hi = g_e1hi; K = SHAPEC; OUT = SC_HID;
        } else {
            r -= 1024;
            e = r >> 5; int q = r & 31;
            k0 = (q & 7) * 32; o0 = (q >> 3) * 32;
            src = W2; hi = g_e2hi; K = SC_HID; OUT = SC_OUT;
        }
        const float* s = src + (size_t)e * K * OUT;
#pragma unroll
        for (int i = ty; i < 32; i += 8)
            t[i][tx] = s[(size_t)(k0 + i) * OUT + o0 + tx];
        __syncthreads();
        size_t base = (size_t)e * OUT * K + (size_t)o0 * K + k0;
#pragma unroll
        for (int i = ty; i < 32; i += 8)
            hi[base + (size_t)i * K + tx] = __float2half_rn(t[tx][i]);
    } else if (bi < PREP_T3) {
        // ---- head channels + pad -> a0hi ----
        int i = (bi - PREP_T2) * 256 + tid;
        int p = i >> 5, s = i & 31;
        float v = 0.f;
        int col;
        if (s < 8) {
            int b = p >> 10, n = p & 1023;
            v = x[(size_t)b * XCH * NPTS + (size_t)s * NPTS + n];
            col = s;
        } else {
            col = 128 + s;
        }
        g_a0hi[(size_t)p * K0PAD + col] = __float2half_rn(v);
    } else {
        // ---- conv weight convert (hi only, 4 elems/thread, float4) ----
        int r = bi - PREP_T3;
        const float* w; h16* hi; int Kin, Kpad, total4, i4;
        if (r < WS_NB1) {
            w = Wc1; hi = g_w1hi; Kin = 136; Kpad = K0PAD;
            total4 = C1OUT * K0PAD / 4; i4 = r * 256 + tid;
        } else if (r < WS_NB1 + WS_NB2) {
            w = Wc2; hi = g_w2hi; Kin = C1OUT; Kpad = C1OUT;
            total4 = C2OUT * C1OUT / 4; i4 = (r - WS_NB1) * 256 + tid;
        } else {
            w = Wc3; hi = g_w3hi; Kin = C2OUT; Kpad = C2OUT;
            total4 = C3OUT * C2OUT / 4; i4 = (r - WS_NB1 - WS_NB2) * 256 + tid;
        }
        if (i4 >= total4) return;
        int i = i4 * 4;
        int c = i / Kpad, k = i - c * Kpad;
        float4 v = make_float4(0.f, 0.f, 0.f, 0.f);
        if (k < Kin)
            v = *(const float4*)(w + (size_t)c * Kin + k);
        uint2 pk;
        pk.x = pack2h(__float2half_rn(v.x), __float2half_rn(v.y));
        pk.y = pack2h(__float2half_rn(v.z), __float2half_rn(v.w));
        *(uint2*)(hi + i) = pk;
    }
}

// ---------------- 2. fused expert MLP (hi-only, 3-stage ring) ----------------
// smem: RING 3 x 25600 @0 (A 5120 | B1 20480); stage2 reuses ring (B2 10240/slot)
// H 40960 @76800 -> ESMEM 117760
#define ERING  25600
#define ESM_H  76800
#define ESMEM  117760

__global__ void __launch_bounds__(256) k_expert_mma(
    const float* __restrict__ b1g, const float* __restrict__ b2g)
{
    int t = blockIdx.x;
    if (t >= g_nTiles) return;
    int e = g_tileExpert[t], start = g_tileStart[t], len = g_tileLen[t];

    extern __shared__ char smraw[];
    __shared__ int pidx[ETILE];
    __shared__ int gidx[ETILE];

    int tid = threadIdx.x, lane = tid & 31, wid = tid >> 5;
    uint32_t sb = smem_u32(smraw);

    if (tid < ETILE) {
        int pi = (tid < len) ? g_idx[start + tid] : -1;
        pidx[tid] = pi;
        gidx[tid] = pi < 0 ? 0 : pi;
    }
    __syncthreads();

    const h16* w1h = g_e1hi + (size_t)e * SC_HID * SHAPEC;
    const h16* w2h = g_e2hi + (size_t)e * SC_OUT * SC_HID;

    auto loadS1 = [&](int ks, int st) {
        uint32_t sbs = sb + st * ERING;
        {
            int row = tid >> 2, ch = tid & 3;
            const h16* src = g_xhi + (size_t)gidx[row] * SHAPEC + ks * 32 + ch * 8;
            CP_ASYNC16(sbs + (uint32_t)row * 80 + ch * 16, src);
        }
#pragma unroll
        for (int r = 0; r < 4; r++) {
            int id = tid + r * 256;
            int row = id >> 2, ch = id & 3;
            const h16* src = w1h + (size_t)row * SHAPEC + ks * 32 + ch * 8;
            CP_ASYNC16(sbs + 5120 + (uint32_t)row * 80 + ch * 16, src);
        }
        CP_COMMIT();
    };
    auto loadS2 = [&](int ks, int st) {
        uint32_t sbs = sb + st * 10240;
#pragma unroll
        for (int r = 0; r < 2; r++) {
            int id = tid + r * 256;
            int row = id >> 2, ch = id & 3;
            const h16* src = w2h + (size_t)row * SC_HID + ks * 32 + ch * 8;
            CP_ASYNC16(sbs + (uint32_t)row * 80 + ch * 16, src);
        }
        CP_COMMIT();
    };

    // ======== stage 1: h[64,256] = relu(A @ W1T + b1), ring ====
    {
        float acc[4][4][4];
#pragma unroll
        for (int a = 0; a < 4; a++)
#pragma unroll
            for (int b = 0; b < 4; b++)
#pragma unroll
                for (int c = 0; c < 4; c++) acc[a][b][c] = 0.f;

        uint32_t rowA = (uint32_t)(lane & 15) * 80 + (lane >> 4) * 16;
        uint32_t rowB = (uint32_t)(wid * 32 + (lane & 15)) * 80 + (lane >> 4) * 16;

        loadS1(0, 0);
        loadS1(1, 1);
        for (int ks = 0; ks < 8; ks++) {
            if (ks < 7) CP_WAIT1(); else CP_WAIT0();
            __syncthreads();
            if (ks + 2 < 8) loadS1(ks + 2, (ks + 2) % 3);
            uint32_t sba = sb + (ks % 3) * ERING;
            uint32_t sbb = sba + 5120;
#pragma unroll
            for (int s = 0; s < 2; s++) {
                uint32_t aH[4][4], bH[2][4];
#pragma unroll
                for (int mf = 0; mf < 4; mf++) {
                    uint32_t ad = sba + rowA + (uint32_t)mf * (16 * 80) + s * 32;
                    LDSM4(aH[mf], ad);
                }
#pragma unroll
                for (int p = 0; p < 2; p++) {
                    uint32_t bd = sbb + rowB + (uint32_t)p * (16 * 80) + s * 32;
                    LDSM4(bH[p], bd);
                }
#pragma unroll
                for (int mf = 0; mf < 4; mf++)
#pragma unroll
                    for (int nf = 0; nf < 4; nf++) {
                        int p = nf >> 1, sel = nf & 1;
                        mma_f32(acc[mf][nf], aH[mf], bH[p][sel], bH[p][sel + 2]);
                    }
            }
        }

        // all warps done with final ring reads before stage-2 loads overwrite
        __syncthreads();
        loadS2(0, 0);
        loadS2(1, 1);

        // epilogue1: +b1, relu -> smem H (overlaps stage-2 weight loads)
        const float* b1 = b1g + e * SC_HID;
#pragma unroll
        for (int mf = 0; mf < 4; mf++) {
            int row = mf * 16 + (lane >> 2);
#pragma unroll
            for (int nf = 0; nf < 4; nf++) {
                int col = wid * 32 + nf * 8 + 2 * (lane & 3);
                float b0v = b1[col], b1v = b1[col + 1];
                float v0 = fmaxf(acc[mf][nf][0] + b0v, 0.f);
                float v1 = fmaxf(acc[mf][nf][1] + b1v, 0.f);
                float v2 = fmaxf(acc[mf][nf][2] + b0v, 0.f);
                float v3 = fmaxf(acc[mf][nf][3] + b1v, 0.f);
                int ks = col >> 5, cw = col & 31;
                uint32_t off = (uint32_t)ks * 5120 + (uint32_t)row * 80 + cw * 2;
                *(uint32_t*)(smraw + ESM_H + off)
                    = pack2h(__float2half_rn(v0), __float2half_rn(v1));
                *(uint32_t*)(smraw + ESM_H + off + 8 * 80)
                    = pack2h(__float2half_rn(v2), __float2half_rn(v3));
            }
        }
    }
    __syncthreads();

    // ======== stage 2: o[64,128] = h @ W2T + b2, ring ====
    {
        int warp_m = wid & 1, warp_n = wid >> 1;
        float acc[2][4][4];
#pragma unroll
        for (int a = 0; a < 2; a++)
#pragma unroll
            for (int b = 0; b < 4; b++)
#pragma unroll
                for (int c = 0; c < 4; c++) acc[a][b][c] = 0.f;

        uint32_t rowA = (uint32_t)(warp_m * 32 + (lane & 15)) * 80 + (lane >> 4) * 16;
        uint32_t rowB = (uint32_t)(warp_n * 32 + (lane & 15)) * 80 + (lane >> 4) * 16;

        for (int ks = 0; ks < 8; ks++) {
            if (ks < 7) CP_WAIT1(); else CP_WAIT0();
            __syncthreads();
            if (ks + 2 < 8) loadS2(ks + 2, (ks + 2) % 3);
            uint32_t hbase = sb + ESM_H + (uint32_t)ks * 5120;
            uint32_t sbb = sb + (ks % 3) * 10240;
#pragma unroll
            for (int s = 0; s < 2; s++) {
                uint32_t aH[2][4], bH[2][4];
#pragma unroll
                for (int mf = 0; mf < 2; mf++) {
                    uint32_t ad = hbase + rowA + (uint32_t)mf * (16 * 80) + s * 32;
                    LDSM4(aH[mf], ad);
                }
#pragma unroll
                for (int p = 0; p < 2; p++) {
                    uint32_t bd = sbb + rowB + (uint32_t)p * (16 * 80) + s * 32;
                    LDSM4(bH[p], bd);
                }
#pragma unroll
                for (int mf = 0; mf < 2; mf++)
#pragma unroll
                    for (int nf = 0; nf < 4; nf++) {
                        int p = nf >> 1, sel = nf & 1;
                        mma_f32(acc[mf][nf], aH[mf], bH[p][sel], bH[p][sel + 2]);
                    }
            }
        }

        const float* b2 = b2g + e * SC_OUT;
#pragma unroll
        for (int mf = 0; mf < 2; mf++) {
            int row = warp_m * 32 + mf * 16 + (lane >> 2);
#pragma unroll
            for (int nf = 0; nf < 4; nf++) {
                int col = warp_n * 32 + nf * 8 + 2 * (lane & 3);
                float b0v = b2[col], b1v = b2[col + 1];
                float v0 = acc[mf][nf][0] + b0v, v1 = acc[mf][nf][1] + b1v;
                float v2 = acc[mf][nf][2] + b0v, v3 = acc[mf][nf][3] + b1v;
                int pi0 = pidx[row], pi1 = pidx[row + 8];
                if (pi0 >= 0)
                    *(uint32_t*)(g_a0hi + (size_t)pi0 * K0PAD + HEADC + col)
                        = pack2h(__float2half_rn(v0), __float2half_rn(v1));
                if (pi1 >= 0)
                    *(uint32_t*)(g_a0hi + (size_t)pi1 * K0PAD + HEADC + col)
                        = pack2h(__float2half_rn(v2), __float2half_rn(v3));
            }
        }
    }
}

// ---------------- 3. f16 mma GEMM: hi-only, FR*32-row tiles ----------------
template <int KTOT, int RELU, int SPLIT, int FR>
__global__ void __launch_bounds__(256, 2) gemm_mma(
    const h16* __restrict__ aHi, const h16* __restrict__ wHi,
    const float* __restrict__ bias,
    h16* __restrict__ oHi, int KOUT)
{
    extern __shared__ char smraw[];
    const int NK = KTOT / 32;
    const int MTILE = FR * 32;
    const int ASZ = MTILE * 80;
    const int STG = ASZ + 10240;
    int tid = threadIdx.x, lane = tid & 31, wid = tid >> 5;
    int warp_m = wid & 1, warp_n = wid >> 1;     // 2 x 4 warps
    int m0 = blockIdx.x * MTILE, c0 = blockIdx.y * 128;

    uint32_t smBase = smem_u32(smraw);
    uint32_t rowA = (uint32_t)(warp_m * (FR * 16) + (lane & 15)) * 80 + (lane >> 4) * 16;
    uint32_t rowB = (uint32_t)(warp_n * 32 + (lane & 15)) * 80 + (lane >> 4) * 16;

    float acc[FR][4][4];
#pragma unroll
    for (int a = 0; a < FR; a++)
#pragma unroll
        for (int b = 0; b < 4; b++)
#pragma unroll
            for (int c = 0; c < 4; c++) acc[a][b][c] = 0.f;

    auto loadStage = [&](int ks, int st) {
        uint32_t sbs = smBase + st * STG;
#pragma unroll
        for (int i = 0; i < MTILE * 4; i += 256) {
            int c = tid + i;
            int row = c >> 2, ch = c & 3;
            const h16* src = aHi + (size_t)(m0 + row) * KTOT + ks * 32 + ch * 8;
            CP_ASYNC16(sbs + (uint32_t)row * 80 + ch * 16, src);
        }
#pragma unroll
        for (int i = 0; i < 2; i++) {
            int c = tid + i * 256;
            int row = c >> 2, ch = c & 3;
            const h16* src = wHi + (size_t)(c0 + row) * KTOT + ks * 32 + ch * 8;
            CP_ASYNC16(sbs + ASZ + (uint32_t)row * 80 + ch * 16, src);
        }
        CP_COMMIT();
    };

    loadStage(0, 0);
    if (NK > 1) loadStage(1, 1);
    for (int ks = 0; ks < NK; ks++) {
        if (ks < NK - 1) CP_WAIT1(); else CP_WAIT0();
        __syncthreads();
        if (ks + 2 < NK) loadStage(ks + 2, (ks + 2) % 3);

        uint32_t sbs = smBase + (ks % 3) * STG;
#pragma unroll
        for (int s = 0; s < 2; s++) {
            uint32_t aH[FR][4], bH[2][4];
#pragma unroll
            for (int mf = 0; mf < FR; mf++) {
                uint32_t ad = sbs + rowA + (uint32_t)mf * (16 * 80) + s * 32;
                LDSM4(aH[mf], ad);
            }
#pragma unroll
            for (int p = 0; p < 2; p++) {
                uint32_t bd = sbs + ASZ + rowB + (uint32_t)p * (16 * 80) + s * 32;
                LDSM4(bH[p], bd);
            }
#pragma unroll
            for (int mf = 0; mf < FR; mf++)
#pragma unroll
                for (int nf = 0; nf < 4; nf++) {
                    int p = nf >> 1, sel = nf & 1;
                    mma_f32(acc[mf][nf], aH[mf], bH[p][sel], bH[p][sel + 2]);
                }
        }
    }

    if (SPLIT) {
#pragma unroll
        for (int mf = 0; mf < FR; mf++) {
            int row = m0 + warp_m * (FR * 16) + mf * 16 + (lane >> 2);
#pragma unroll
            for (int nf = 0; nf < 4; nf++) {
                int col = c0 + warp_n * 32 + nf * 8 + 2 * (lane & 3);
                float b0v = bias[col], b1v = bias[col + 1];
                float v0 = acc[mf][nf][0] + b0v, v1 = acc[mf][nf][1] + b1v;
                float v2 = acc[mf][nf][2] + b0v, v3 = acc[mf][nf][3] + b1v;
                if (RELU) {
                    v0 = fmaxf(v0, 0.f); v1 = fmaxf(v1, 0.f);
                    v2 = fmaxf(v2, 0.f); v3 = fmaxf(v3, 0.f);
                }
                *(uint32_t*)(oHi + (size_t)row * KOUT + col)
                    = pack2h(__float2half_rn(v0), __float2half_rn(v1));
                *(uint32_t*)(oHi + (size_t)(row + 8) * KOUT + col)
                    = pack2h(__float2half_rn(v2), __float2half_rn(v3));
            }
        }
    } else {
        // ---- fused max-pool epilogue: partial max over MTILE rows ----
        __syncthreads();
        float* pm = (float*)smraw;               // [2][128]
#pragma unroll
        for (int nf = 0; nf < 4; nf++) {
            float c0m = -FLT_MAX, c1m = -FLT_MAX;
#pragma unroll
            for (int mf = 0; mf < FR; mf++) {
                int col = c0 + warp_n * 32 + nf * 8 + 2 * (lane & 3);
                float b0v = bias[col], b1v = bias[col + 1];
                c0m = fmaxf(c0m, fmaxf(acc[mf][nf][0] + b0v, acc[mf][nf][2] + b0v));
                c1m = fmaxf(c1m, fmaxf(acc[mf][nf][1] + b1v, acc[mf][nf][3] + b1v));
            }
#pragma unroll
            for (int o = 4; o < 32; o <<= 1) {
                c0m = fmaxf(c0m, __shfl_xor_sync(0xFFFFFFFFu, c0m, o));
                c1m = fmaxf(c1m, __shfl_xor_sync(0xFFFFFFFFu, c1m, o));
            }
            if (lane < 4) {
                int cc = warp_n * 32 + nf * 8 + 2 * lane;
                pm[warp_m * 128 + cc]     = c0m;
                pm[warp_m * 128 + cc + 1] = c1m;
            }
        }
        __syncthreads();
        if (tid < 64) {
            int cc = tid * 2;
            float m0v = fmaxf(pm[cc],     pm[128 + cc]);
            float m1v = fmaxf(pm[cc + 1], pm[128 + cc + 1]);
            int b = m0 >> 10, part = (m0 >> 7) & (NPART - 1);
            *(float2*)(g_part + (size_t)(b * NPART + part) * C3OUT + c0 + cc)
                = make_float2(m0v, m1v);
        }
    }
}

// ---------------- 4. decoder MLP (POOL=1 builds latent from g_part) --------
template <int RELU, int POOL>
__global__ void __launch_bounds__(256) mlp8(
    const float* __restrict__ A, const float* __restrict__ W,
    const float* __restrict__ bias, float* __restrict__ Out,
    int K, int N, float* __restrict__ extra, int we)
{
    extern __shared__ float Ash[];
    __shared__ float red[256 * 8];
    int tid = threadIdx.x;
    if (POOL) {
        for (int i = tid; i < 8 * 1024; i += 256) {
            int b = i >> 10, c = i & 1023;
            const float* gp = g_part + (size_t)(b * NPART) * C3OUT + c;
            float m = gp[0];
#pragma unroll
            for (int part = 1; part < NPART; part++)
                m = fmaxf(m, gp[(size_t)part * C3OUT]);
            Ash[i] = m;
            if (we && blockIdx.x == 0) extra[i] = m;
        }
    } else {
        for (int i = tid; i < 8 * K / 4; i += 256)
            ((float4*)Ash)[i] = ((const float4*)A)[i];
    }
    __syncthreads();

    int col   = blockIdx.x * 32 + (tid & 31);
    int slice = tid >> 5;
    int kPer  = K >> 3;
    int k0    = slice * kPer;

    float acc[8];
#pragma unroll
    for (int bb = 0; bb < 8; bb++) acc[bb] = 0.f;

    for (int k = k0; k < k0 + kPer; k += 16) {
        float w[16];
#pragma unroll
        for (int j = 0; j < 16; j++)
            w[j] = W[(size_t)(k + j) * N + col];
#pragma unroll
        for (int bb = 0; bb < 8; bb++) {
            const float4* a4p = (const float4*)(Ash + bb * K + k);
#pragma unroll
            for (int q = 0; q < 4; q++) {
                float4 a = a4p[q];
                acc[bb] = fmaf(a.x, w[q * 4 + 0], acc[bb]);
                acc[bb] = fmaf(a.y, w[q * 4 + 1], acc[bb]);
                acc[bb] = fmaf(a.z, w[q * 4 + 2], acc[bb]);
                acc[bb] = fmaf(a.w, w[q * 4 + 3], acc[bb]);
            }
        }
    }
#pragma unroll
    for (int bb = 0; bb < 8; bb++) red[tid * 8 + bb] = acc[bb];
    __syncthreads();
    if (tid < 32) {
        float bsv = bias[col];
#pragma unroll
        for (int bb = 0; bb < 8; bb++) {
            float v = bsv;
#pragma unroll
            for (int s = 0; s < 8; s++)
                v += red[(tid + s * 32) * 8 + bb];
            if (RELU) v = fmaxf(v, 0.f);
            Out[(size_t)bb * N + col] = v;
        }
    }
}

// ---------------- launch ----------------
extern "C" void kernel_launch(void* const* d_in, const int* in_sizes, int n_in,
                              void* d_out, int out_size) {
    const float* x    = (const float*)d_in[0];
    const int*   cats = (const int*)  d_in[1];
    const float* W1   = (const float*)d_in[2];
    const float* b1   = (const float*)d_in[3];
    const float* W2   = (const float*)d_in[4];
    const float* b2   = (const float*)d_in[5];
    const float* Wc1  = (const float*)d_in[6];
    const float* bc1  = (const float*)d_in[7];
    const float* Wc2  = (const float*)d_in[8];
    const float* bc2  = (const float*)d_in[9];
    const float* Wc3  = (const float*)d_in[10];
    const float* bc3  = (const float*)d_in[11];
    const float* Wd1  = (const float*)d_in[12];
    const float* bd1  = (const float*)d_in[13];
    const float* Wd2  = (const float*)d_in[14];
    const float* bd2  = (const float*)d_in[15];
    const float* Wd3  = (const float*)d_in[16];
    const float* bd3  = (const float*)d_in[17];
    float* out = (float*)d_out;

    const int GS2 = 3 * (64 * 80 + 10240);    // FR=2 stages
    const int GS4 = 3 * (128 * 80 + 10240);   // FR=4 stages

    cudaFuncSetAttribute(k_expert_mma, cudaFuncAttributeMaxDynamicSharedMemorySize, ESMEM);
    cudaFuncSetAttribute(mlp8<1, 1>, cudaFuncAttributeMaxDynamicSharedMemorySize, 65536);
    cudaFuncSetAttribute(mlp8<1, 0>, cudaFuncAttributeMaxDynamicSharedMemorySize, 65536);
    cudaFuncSetAttribute(mlp8<0, 0>, cudaFuncAttributeMaxDynamicSharedMemorySize, 65536);
    cudaFuncSetAttribute(gemm_mma<K0PAD, 1, 1, 2>, cudaFuncAttributeMaxDynamicSharedMemorySize, GS2);
    cudaFuncSetAttribute(gemm_mma<C1OUT, 1, 1, 4>, cudaFuncAttributeMaxDynamicSharedMemorySize, GS4);
    cudaFuncSetAttribute(gemm_mma<C2OUT, 0, 0, 4>, cudaFuncAttributeMaxDynamicSharedMemorySize, GS4);

    h16 *p_a0h, *p_a1h, *p_a2h, *p_w1h, *p_w2h, *p_w3h;
    float *p_d1, *p_d2;
    cudaGetSymbolAddress((void**)&p_a0h, g_a0hi);
    cudaGetSymbolAddress((void**)&p_a1h, g_a1hi);
    cudaGetSymbolAddress((void**)&p_a2h, g_a2hi);
    cudaGetSymbolAddress((void**)&p_w1h, g_w1hi);
    cudaGetSymbolAddress((void**)&p_w2h, g_w2hi);
    cudaGetSymbolAddress((void**)&p_w3h, g_w3hi);
    cudaGetSymbolAddress((void**)&p_d1,  g_d1);
    cudaGetSymbolAddress((void**)&p_d2,  g_d2);

    // prep (build fused as final block), expert, conv stack
    k_prep<<<PREP_NB, 256>>>(x, cats, W1, W2, Wc1, Wc2, Wc3);
    k_expert_mma<<<MAXTILES, 256, ESMEM>>>(b1, b2);

    gemm_mma<K0PAD, 1, 1, 2><<<dim3(128, C1OUT / 128), 256, GS2>>>(
        p_a0h, p_w1h, bc1, p_a1h, C1OUT);
    gemm_mma<C1OUT, 1, 1, 4><<<dim3(64, C2OUT / 128), 256, GS4>>>(
        p_a1h, p_w2h, bc2, p_a2h, C2OUT);
    gemm_mma<C2OUT, 0, 0, 4><<<dim3(64, C3OUT / 128), 256, GS4>>>(
        p_a2h, p_w3h, bc3, (h16*)0, C3OUT);

    // decoder: mlp1 fuses the final pool reduction (POOL=1)
    int write_extra = (out_size >= 65536 + 8192) ? 1 : 0;
    mlp8<1, 1><<<DEC1 / 32, 256, 8 * DEC1 * 4>>>(
        (const float*)0, Wd1, bd1, p_d1, DEC1, DEC1, out + 65536, write_extra);
    mlp8<1, 0><<<DEC2 / 32, 256, 8 * DEC1 * 4>>>(
        p_d1, Wd2, bd2, p_d2, DEC1, DEC2, (float*)0, 0);
    mlp8<0, 0><<<DEC3 / 32, 256, 8 * DEC2 * 4>>>(
        p_d2, Wd3, bd3, out, DEC2, DEC3, (float*)0, 0);
}

// round 17
// speedup vs baseline: 1.0579x; 1.0579x over previous
#include <cuda_runtime.h>
#include <cuda_fp16.h>
#include <float.h>
#include <stdint.h>

// ---------------- problem constants ----------------
#define BATCH      8
#define NPTS       1024
#define NPOINTS    (BATCH * NPTS)        // 8192
#define HEADC      8
#define SHAPEC     256
#define XCH        (HEADC + SHAPEC)      // 264
#define NEXPERT    16
#define SC_HID     256
#define SC_OUT     128
#define K0PAD      160                   // 136 padded to 160
#define C1OUT      256
#define C2OUT      512
#define C3OUT      1024
#define DEC1       1024
#define DEC2       2048
#define DEC3       8192
#define ETILE      64
#define MAXTILES   (NPOINTS / ETILE + NEXPERT)   // 144
#define NPART      8                     // pool partials per batch (1024/128)

typedef __half h16;

// ---------------- scratch (device globals; no runtime alloc) ----------------
__device__ __align__(256) h16 g_xhi[NPOINTS * SHAPEC];
__device__ __align__(256) h16 g_a0hi[NPOINTS * K0PAD];
__device__ __align__(256) h16 g_a1hi[NPOINTS * C1OUT];
__device__ __align__(256) h16 g_a2hi[NPOINTS * C2OUT];
__device__ __align__(256) h16 g_w1hi[C1OUT * K0PAD];
__device__ __align__(256) h16 g_w2hi[C2OUT * C1OUT];
__device__ __align__(256) h16 g_w3hi[C3OUT * C2OUT];
__device__ __align__(256) h16 g_e1hi[NEXPERT * SC_HID * SHAPEC];
__device__ __align__(256) h16 g_e2hi[NEXPERT * SC_OUT * SC_HID];
__device__ float g_part[BATCH * NPART * C3OUT];
__device__ float g_d1[BATCH * DEC1];
__device__ float g_d2[BATCH * DEC2];
__device__ int   g_idx[NPOINTS];
__device__ int   g_tileExpert[MAXTILES];
__device__ int   g_tileStart[MAXTILES];
__device__ int   g_tileLen[MAXTILES];
__device__ int   g_nTiles;

// ---------------- ptx helpers (sm_80-safe) ----------------
__device__ __forceinline__ uint32_t smem_u32(const void* p) {
    uint32_t a;
    asm("{ .reg .u64 t; cvta.to.shared.u64 t, %1; cvt.u32.u64 %0, t; }" : "=r"(a) : "l"(p));
    return a;
}
#define CP_ASYNC16(dst, src) \
    asm volatile("cp.async.cg.shared.global [%0], [%1], 16;" :: "r"(dst), "l"(src))
#define CP_COMMIT() asm volatile("cp.async.commit_group;" ::: "memory")
#define CP_WAIT0()  asm volatile("cp.async.wait_group 0;" ::: "memory")
#define CP_WAIT1()  asm volatile("cp.async.wait_group 1;" ::: "memory")

#define LDSM4(r, addr) \
    asm volatile("ldmatrix.sync.aligned.m8n8.x4.shared.b16 {%0,%1,%2,%3}, [%4];" \
        : "=r"((r)[0]), "=r"((r)[1]), "=r"((r)[2]), "=r"((r)[3]) : "r"(addr))

__device__ __forceinline__ void mma_f32(float* d, const uint32_t* a,
                                        uint32_t b0, uint32_t b1) {
    asm volatile(
        "mma.sync.aligned.m16n8k16.row.col.f32.f16.f16.f32 "
        "{%0,%1,%2,%3}, {%4,%5,%6,%7}, {%8,%9}, {%0,%1,%2,%3};"
        : "+f"(d[0]), "+f"(d[1]), "+f"(d[2]), "+f"(d[3])
        : "r"(a[0]), "r"(a[1]), "r"(a[2]), "r"(a[3]), "r"(b0), "r"(b1));
}

__device__ __forceinline__ uint32_t pack2h(h16 a, h16 b) {
    __half2 t; t.x = a; t.y = b;
    return *(uint32_t*)&t;
}

// ---------------- 1. fused prep: transpose | tsplit | head | wconv ---------
#define PREP_T1 2048
#define PREP_T2 3584
#define PREP_T3 4608
#define WS_NB1 40
#define WS_NB2 128
#define WS_NB3 512
#define PREP_NB (PREP_T3 + WS_NB1 + WS_NB2 + WS_NB3)   // 5288

__global__ void __launch_bounds__(256) k_prep(
    const float* __restrict__ x,
    const float* __restrict__ W1, const float* __restrict__ W2,
    const float* __restrict__ Wc1, const float* __restrict__ Wc2,
    const float* __restrict__ Wc3)
{
    __shared__ float t[32][33];
    int bi = blockIdx.x;
    int tid = threadIdx.x;
    int tx = tid & 31, ty = tid >> 5;

    if (bi < PREP_T1) {
        // ---- transpose x shape feats -> g_xhi ----
        int idx = bi;
        int cB = (idx & 7) * 32;
        int nB = ((idx >> 3) & 31) * 32;
        int b  = idx >> 8;
        const float* xb = x + (size_t)b * XCH * NPTS;
#pragma unroll
        for (int i = ty; i < 32; i += 8)
            t[i][tx] = xb[(size_t)(HEADC + cB + i) * NPTS + nB + tx];
        __syncthreads();
        size_t base = ((size_t)b * NPTS + nB) * SHAPEC + cB;
#pragma unroll
        for (int i = ty; i < 32; i += 8)
            g_xhi[base + (size_t)i * SHAPEC + tx] = __float2half_rn(t[tx][i]);
    } else if (bi < PREP_T2) {
        // ---- expert weight transpose (hi only) ----
        int r = bi - PREP_T1;
        const float* src; h16 *hi; int K, OUT, e, k0, o0;
        if (r < 1024) {
            e = r >> 6; int q = r & 63;
            k0 = (q & 7) * 32; o0 = (q >> 3) * 32;
            src = W1; hi = g_e1hi; K = SHAPEC; OUT = SC_HID;
        } else {
            r -= 1024;
            e = r >> 5; int q = r & 31;
            k0 = (q & 7) * 32; o0 = (q >> 3) * 32;
            src = W2; hi = g_e2hi; K = SC_HID; OUT = SC_OUT;
        }
        const float* s = src + (size_t)e * K * OUT;
#pragma unroll
        for (int i = ty; i < 32; i += 8)
            t[i][tx] = s[(size_t)(k0 + i) * OUT + o0 + tx];
        __syncthreads();
        size_t base = (size_t)e * OUT * K + (size_t)o0 * K + k0;
#pragma unroll
        for (int i = ty; i < 32; i += 8)
            hi[base + (size_t)i * K + tx] = __float2half_rn(t[tx][i]);
    } else if (bi < PREP_T3) {
        // ---- head channels + pad -> a0hi ----
        int i = (bi - PREP_T2) * 256 + tid;
        int p = i >> 5, s = i & 31;
        float v = 0.f;
        int col;
        if (s < 8) {
            int b = p >> 10, n = p & 1023;
            v = x[(size_t)b * XCH * NPTS + (size_t)s * NPTS + n];
            col = s;
        } else {
            col = 128 + s;
        }
        g_a0hi[(size_t)p * K0PAD + col] = __float2half_rn(v);
    } else {
        // ---- conv weight convert (hi only, 4 elems/thread, float4) ----
        int r = bi - PREP_T3;
        const float* w; h16* hi; int Kin, Kpad, total4, i4;
        if (r < WS_NB1) {
            w = Wc1; hi = g_w1hi; Kin = 136; Kpad = K0PAD;
            total4 = C1OUT * K0PAD / 4; i4 = r * 256 + tid;
        } else if (r < WS_NB1 + WS_NB2) {
            w = Wc2; hi = g_w2hi; Kin = C1OUT; Kpad = C1OUT;
            total4 = C2OUT * C1OUT / 4; i4 = (r - WS_NB1) * 256 + tid;
        } else {
            w = Wc3; hi = g_w3hi; Kin = C2OUT; Kpad = C2OUT;
            total4 = C3OUT * C2OUT / 4; i4 = (r - WS_NB1 - WS_NB2) * 256 + tid;
        }
        if (i4 >= total4) return;
        int i = i4 * 4;
        int c = i / Kpad, k = i - c * Kpad;
        float4 v = make_float4(0.f, 0.f, 0.f, 0.f);
        if (k < Kin)                                 // groups never straddle (Kin%4==0)
            v = *(const float4*)(w + (size_t)c * Kin + k);
        uint2 pk;
        pk.x = pack2h(__float2half_rn(v.x), __float2half_rn(v.y));
        pk.y = pack2h(__float2half_rn(v.z), __float2half_rn(v.w));
        *(uint2*)(hi + i) = pk;
    }
}

// ---------------- 2. counting sort (warp-aggregated atomics) ----------------
__global__ void k_build(const int* __restrict__ cats) {
    __shared__ int cnt[NEXPERT];
    __shared__ int off[NEXPERT + 1];
    __shared__ int cur[NEXPERT];
    int tid = threadIdx.x, lane = tid & 31;
    if (tid < NEXPERT) cnt[tid] = 0;
    __syncthreads();
    for (int i = tid; i < NPOINTS; i += blockDim.x) {
        int c = cats[i];
        unsigned m = __match_any_sync(0xFFFFFFFFu, c);
        int leader = __ffs(m) - 1;
        if (lane == leader) atomicAdd(&cnt[c], __popc(m));
    }
    __syncthreads();
    if (tid == 0) {
        int s = 0;
        for (int e = 0; e < NEXPERT; e++) { off[e] = s; s += cnt[e]; }
        off[NEXPERT] = s;
        int t = 0;
        for (int e = 0; e < NEXPERT; e++)
            for (int st = off[e]; st < off[e + 1]; st += ETILE) {
                g_tileExpert[t] = e;
                g_tileStart[t]  = st;
                g_tileLen[t]    = min(ETILE, off[e + 1] - st);
                t++;
            }
        g_nTiles = t;
    }
    __syncthreads();
    if (tid < NEXPERT) cur[tid] = off[tid];
    __syncthreads();
    for (int i = tid; i < NPOINTS; i += blockDim.x) {
        int c = cats[i];
        unsigned m = __match_any_sync(0xFFFFFFFFu, c);
        int leader = __ffs(m) - 1;
        int rank = __popc(m & ((1u << lane) - 1u));
        int base = 0;
        if (lane == leader) base = atomicAdd(&cur[c], __popc(m));
        base = __shfl_sync(m, base, leader);
        g_idx[base + rank] = i;
    }
}

// ---------------- 3. fused expert MLP (hi-only) ----------------
// smem: A 2x5120 @0; B 2x20480 @10240; H 40960 @51200 -> 92160 B
#define ESM_A  0
#define ESM_B  10240
#define ESM_H  51200
#define ESMEM  92160

__global__ void __launch_bounds__(256) k_expert_mma(
    const float* __restrict__ b1g, const float* __restrict__ b2g)
{
    int t = blockIdx.x;
    if (t >= g_nTiles) return;
    int e = g_tileExpert[t], start = g_tileStart[t], len = g_tileLen[t];

    extern __shared__ char smraw[];
    __shared__ int pidx[ETILE];
    __shared__ int gidx[ETILE];

    int tid = threadIdx.x, lane = tid & 31, wid = tid >> 5;
    uint32_t sb = smem_u32(smraw);

    if (tid < ETILE) {
        int pi = (tid < len) ? g_idx[start + tid] : -1;
        pidx[tid] = pi;
        gidx[tid] = pi < 0 ? 0 : pi;
    }
    __syncthreads();

    const h16* w1h = g_e1hi + (size_t)e * SC_HID * SHAPEC;
    const h16* w2h = g_e2hi + (size_t)e * SC_OUT * SC_HID;

    auto loadS1 = [&](int ks, int st) {
        {
            int row = tid >> 2, ch = tid & 3;
            const h16* src = g_xhi + (size_t)gidx[row] * SHAPEC + ks * 32 + ch * 8;
            CP_ASYNC16(sb + ESM_A + st * 5120 + (uint32_t)row * 80 + ch * 16, src);
        }
#pragma unroll
        for (int r = 0; r < 4; r++) {
            int id = tid + r * 256;
            int row = id >> 2, ch = id & 3;
            const h16* src = w1h + (size_t)row * SHAPEC + ks * 32 + ch * 8;
            CP_ASYNC16(sb + ESM_B + st * 20480 + (uint32_t)row * 80 + ch * 16, src);
        }
        CP_COMMIT();
    };
    auto loadS2 = [&](int ks, int st) {
#pragma unroll
        for (int r = 0; r < 2; r++) {
            int id = tid + r * 256;
            int row = id >> 2, ch = id & 3;
            const h16* src = w2h + (size_t)row * SC_HID + ks * 32 + ch * 8;
            CP_ASYNC16(sb + ESM_B + st * 10240 + (uint32_t)row * 80 + ch * 16, src);
        }
        CP_COMMIT();
    };

    // ======== stage 1: h[64,256] = relu(A @ W1T + b1) ====
    {
        float acc[4][4][4];
#pragma unroll
        for (int a = 0; a < 4; a++)
#pragma unroll
            for (int b = 0; b < 4; b++)
#pragma unroll
                for (int c = 0; c < 4; c++) acc[a][b][c] = 0.f;

        uint32_t rowA = (uint32_t)(lane & 15) * 80 + (lane >> 4) * 16;
        uint32_t rowB = (uint32_t)(wid * 32 + (lane & 15)) * 80 + (lane >> 4) * 16;

        loadS1(0, 0);
        for (int ks = 0; ks < 8; ks++) {
            CP_WAIT0();
            __syncthreads();
            if (ks + 1 < 8) loadS1(ks + 1, (ks + 1) & 1);
            uint32_t sba = sb + ESM_A + (ks & 1) * 5120;
            uint32_t sbb = sb + ESM_B + (ks & 1) * 20480;
#pragma unroll
            for (int s = 0; s < 2; s++) {
                uint32_t aH[4][4], bH[2][4];
#pragma unroll
                for (int mf = 0; mf < 4; mf++) {
                    uint32_t ad = sba + rowA + (uint32_t)mf * (16 * 80) + s * 32;
                    LDSM4(aH[mf], ad);
                }
#pragma unroll
                for (int p = 0; p < 2; p++) {
                    uint32_t bd = sbb + rowB + (uint32_t)p * (16 * 80) + s * 32;
                    LDSM4(bH[p], bd);
                }
#pragma unroll
                for (int mf = 0; mf < 4; mf++)
#pragma unroll
                    for (int nf = 0; nf < 4; nf++) {
                        int p = nf >> 1, sel = nf & 1;
                        mma_f32(acc[mf][nf], aH[mf], bH[p][sel], bH[p][sel + 2]);
                    }
            }
            __syncthreads();
        }

        loadS2(0, 0);

        const float* b1 = b1g + e * SC_HID;
#pragma unroll
        for (int mf = 0; mf < 4; mf++) {
            int row = mf * 16 + (lane >> 2);
#pragma unroll
            for (int nf = 0; nf < 4; nf++) {
                int col = wid * 32 + nf * 8 + 2 * (lane & 3);
                float b0v = b1[col], b1v = b1[col + 1];
                float v0 = fmaxf(acc[mf][nf][0] + b0v, 0.f);
                float v1 = fmaxf(acc[mf][nf][1] + b1v, 0.f);
                float v2 = fmaxf(acc[mf][nf][2] + b0v, 0.f);
                float v3 = fmaxf(acc[mf][nf][3] + b1v, 0.f);
                int ks = col >> 5, cw = col & 31;
                uint32_t off = (uint32_t)ks * 5120 + (uint32_t)row * 80 + cw * 2;
                *(uint32_t*)(smraw + ESM_H + off)
                    = pack2h(__float2half_rn(v0), __float2half_rn(v1));
                *(uint32_t*)(smraw + ESM_H + off + 8 * 80)
                    = pack2h(__float2half_rn(v2), __float2half_rn(v3));
            }
        }
    }
    __syncthreads();

    // ======== stage 2: o[64,128] = h @ W2T + b2 ====
    {
        int warp_m = wid & 1, warp_n = wid >> 1;
        float acc[2][4][4];
#pragma unroll
        for (int a = 0; a < 2; a++)
#pragma unroll
            for (int b = 0; b < 4; b++)
#pragma unroll
                for (int c = 0; c < 4; c++) acc[a][b][c] = 0.f;

        uint32_t rowA = (uint32_t)(warp_m * 32 + (lane & 15)) * 80 + (lane >> 4) * 16;
        uint32_t rowB = (uint32_t)(warp_n * 32 + (lane & 15)) * 80 + (lane >> 4) * 16;

        for (int ks = 0; ks < 8; ks++) {
            CP_WAIT0();
            __syncthreads();
            if (ks + 1 < 8) loadS2(ks + 1, (ks + 1) & 1);
            uint32_t hbase = sb + ESM_H + (uint32_t)ks * 5120;
            uint32_t sbb = sb + ESM_B + (ks & 1) * 10240;
#pragma unroll
            for (int s = 0; s < 2; s++) {
                uint32_t aH[2][4], bH[2][4];
#pragma unroll
                for (int mf = 0; mf < 2; mf++) {
                    uint32_t ad = hbase + rowA + (uint32_t)mf * (16 * 80) + s * 32;
                    LDSM4(aH[mf], ad);
                }
#pragma unroll
                for (int p = 0; p < 2; p++) {
                    uint32_t bd = sbb + rowB + (uint32_t)p * (16 * 80) + s * 32;
                    LDSM4(bH[p], bd);
                }
#pragma unroll
                for (int mf = 0; mf < 2; mf++)
#pragma unroll
                    for (int nf = 0; nf < 4; nf++) {
                        int p = nf >> 1, sel = nf & 1;
                        mma_f32(acc[mf][nf], aH[mf], bH[p][sel], bH[p][sel + 2]);
                    }
            }
            __syncthreads();
        }

        const float* b2 = b2g + e * SC_OUT;
#pragma unroll
        for (int mf = 0; mf < 2; mf++) {
            int row = warp_m * 32 + mf * 16 + (lane >> 2);
#pragma unroll
            for (int nf = 0; nf < 4; nf++) {
                int col = warp_n * 32 + nf * 8 + 2 * (lane & 3);
                float b0v = b2[col], b1v = b2[col + 1];
                float v0 = acc[mf][nf][0] + b0v, v1 = acc[mf][nf][1] + b1v;
                float v2 = acc[mf][nf][2] + b0v, v3 = acc[mf][nf][3] + b1v;
                int pi0 = pidx[row], pi1 = pidx[row + 8];
                if (pi0 >= 0)
                    *(uint32_t*)(g_a0hi + (size_t)pi0 * K0PAD + HEADC + col)
                        = pack2h(__float2half_rn(v0), __float2half_rn(v1));
                if (pi1 >= 0)
                    *(uint32_t*)(g_a0hi + (size_t)pi1 * K0PAD + HEADC + col)
                        = pack2h(__float2half_rn(v2), __float2half_rn(v3));
            }
        }
    }
}

// ---------------- 4. f16 mma GEMM: hi-only, FR*32-row tiles ----------------
template <int KTOT, int RELU, int SPLIT, int FR>
__global__ void __launch_bounds__(256, 2) gemm_mma(
    const h16* __restrict__ aHi, const h16* __restrict__ wHi,
    const float* __restrict__ bias,
    h16* __restrict__ oHi, int KOUT)
{
    extern __shared__ char smraw[];
    const int NK = KTOT / 32;
    const int MTILE = FR * 32;
    const int ASZ = MTILE * 80;
    const int STG = ASZ + 10240;
    int tid = threadIdx.x, lane = tid & 31, wid = tid >> 5;
    int warp_m = wid & 1, warp_n = wid >> 1;     // 2 x 4 warps
    int m0 = blockIdx.x * MTILE, c0 = blockIdx.y * 128;

    uint32_t smBase = smem_u32(smraw);
    uint32_t rowA = (uint32_t)(warp_m * (FR * 16) + (lane & 15)) * 80 + (lane >> 4) * 16;
    uint32_t rowB = (uint32_t)(warp_n * 32 + (lane & 15)) * 80 + (lane >> 4) * 16;

    float acc[FR][4][4];
#pragma unroll
    for (int a = 0; a < FR; a++)
#pragma unroll
        for (int b = 0; b < 4; b++)
#pragma unroll
            for (int c = 0; c < 4; c++) acc[a][b][c] = 0.f;

    auto loadStage = [&](int ks, int st) {
        uint32_t sbs = smBase + st * STG;
#pragma unroll
        for (int i = 0; i < MTILE * 4; i += 256) {
            int c = tid + i;
            int row = c >> 2, ch = c & 3;
            const h16* src = aHi + (size_t)(m0 + row) * KTOT + ks * 32 + ch * 8;
            CP_ASYNC16(sbs + (uint32_t)row * 80 + ch * 16, src);
        }
#pragma unroll
        for (int i = 0; i < 2; i++) {
            int c = tid + i * 256;
            int row = c >> 2, ch = c & 3;
            const h16* src = wHi + (size_t)(c0 + row) * KTOT + ks * 32 + ch * 8;
            CP_ASYNC16(sbs + ASZ + (uint32_t)row * 80 + ch * 16, src);
        }
        CP_COMMIT();
    };

    loadStage(0, 0);
    if (NK > 1) loadStage(1, 1);
    for (int ks = 0; ks < NK; ks++) {
        if (ks < NK - 1) CP_WAIT1(); else CP_WAIT0();
        __syncthreads();
        if (ks + 2 < NK) loadStage(ks + 2, (ks + 2) % 3);

        uint32_t sbs = smBase + (ks % 3) * STG;
#pragma unroll
        for (int s = 0; s < 2; s++) {
            uint32_t aH[FR][4], bH[2][4];
#pragma unroll
            for (int mf = 0; mf < FR; mf++) {
                uint32_t ad = sbs + rowA + (uint32_t)mf * (16 * 80) + s * 32;
                LDSM4(aH[mf], ad);
            }
#pragma unroll
            for (int p = 0; p < 2; p++) {
                uint32_t bd = sbs + ASZ + rowB + (uint32_t)p * (16 * 80) + s * 32;
                LDSM4(bH[p], bd);
            }
#pragma unroll
            for (int mf = 0; mf < FR; mf++)
#pragma unroll
                for (int nf = 0; nf < 4; nf++) {
                    int p = nf >> 1, sel = nf & 1;
                    mma_f32(acc[mf][nf], aH[mf], bH[p][sel], bH[p][sel + 2]);
                }
        }
    }

    if (SPLIT) {
#pragma unroll
        for (int mf = 0; mf < FR; mf++) {
            int row = m0 + warp_m * (FR * 16) + mf * 16 + (lane >> 2);
#pragma unroll
            for (int nf = 0; nf < 4; nf++) {
                int col = c0 + warp_n * 32 + nf * 8 + 2 * (lane & 3);
                float b0v = bias[col], b1v = bias[col + 1];
                float v0 = acc[mf][nf][0] + b0v, v1 = acc[mf][nf][1] + b1v;
                float v2 = acc[mf][nf][2] + b0v, v3 = acc[mf][nf][3] + b1v;
                if (RELU) {
                    v0 = fmaxf(v0, 0.f); v1 = fmaxf(v1, 0.f);
                    v2 = fmaxf(v2, 0.f); v3 = fmaxf(v3, 0.f);
                }
                *(uint32_t*)(oHi + (size_t)row * KOUT + col)
                    = pack2h(__float2half_rn(v0), __float2half_rn(v1));
                *(uint32_t*)(oHi + (size_t)(row + 8) * KOUT + col)
                    = pack2h(__float2half_rn(v2), __float2half_rn(v3));
            }
        }
    } else {
        // ---- fused max-pool epilogue: partial max over MTILE rows ----
        __syncthreads();
        float* pm = (float*)smraw;               // [2][128]
#pragma unroll
        for (int nf = 0; nf < 4; nf++) {
            float c0m = -FLT_MAX, c1m = -FLT_MAX;
#pragma unroll
            for (int mf = 0; mf < FR; mf++) {
                int col = c0 + warp_n * 32 + nf * 8 + 2 * (lane & 3);
                float b0v = bias[col], b1v = bias[col + 1];
                c0m = fmaxf(c0m, fmaxf(acc[mf][nf][0] + b0v, acc[mf][nf][2] + b0v));
                c1m = fmaxf(c1m, fmaxf(acc[mf][nf][1] + b1v, acc[mf][nf][3] + b1v));
            }
#pragma unroll
            for (int o = 4; o < 32; o <<= 1) {
                c0m = fmaxf(c0m, __shfl_xor_sync(0xFFFFFFFFu, c0m, o));
                c1m = fmaxf(c1m, __shfl_xor_sync(0xFFFFFFFFu, c1m, o));
            }
            if (lane < 4) {
                int cc = warp_n * 32 + nf * 8 + 2 * lane;
                pm[warp_m * 128 + cc]     = c0m;
                pm[warp_m * 128 + cc + 1] = c1m;
            }
        }
        __syncthreads();
        if (tid < 64) {
            int cc = tid * 2;
            float m0v = fmaxf(pm[cc],     pm[128 + cc]);
            float m1v = fmaxf(pm[cc + 1], pm[128 + cc + 1]);
            int b = m0 >> 10, part = (m0 >> 7) & (NPART - 1);
            *(float2*)(g_part + (size_t)(b * NPART + part) * C3OUT + c0 + cc)
                = make_float2(m0v, m1v);
        }
    }
}

// ---------------- 5. decoder MLP (POOL=1 builds latent from g_part) --------
template <int RELU, int POOL>
__global__ void __launch_bounds__(256) mlp8(
    const float* __restrict__ A, const float* __restrict__ W,
    const float* __restrict__ bias, float* __restrict__ Out,
    int K, int N, float* __restrict__ extra, int we)
{
    extern __shared__ float Ash[];
    __shared__ float red[256 * 8];
    int tid = threadIdx.x;
    if (POOL) {
        for (int i = tid; i < 8 * 1024; i += 256) {
            int b = i >> 10, c = i & 1023;
            const float* gp = g_part + (size_t)(b * NPART) * C3OUT + c;
            float m = gp[0];
#pragma unroll
            for (int part = 1; part < NPART; part++)
                m = fmaxf(m, gp[(size_t)part * C3OUT]);
            Ash[i] = m;
            if (we && blockIdx.x == 0) extra[i] = m;
        }
    } else {
        for (int i = tid; i < 8 * K / 4; i += 256)
            ((float4*)Ash)[i] = ((const float4*)A)[i];
    }
    __syncthreads();

    int col   = blockIdx.x * 32 + (tid & 31);
    int slice = tid >> 5;
    int kPer  = K >> 3;
    int k0    = slice * kPer;

    float acc[8];
#pragma unroll
    for (int bb = 0; bb < 8; bb++) acc[bb] = 0.f;

    for (int k = k0; k < k0 + kPer; k += 16) {
        float w[16];
#pragma unroll
        for (int j = 0; j < 16; j++)
            w[j] = W[(size_t)(k + j) * N + col];
#pragma unroll
        for (int bb = 0; bb < 8; bb++) {
            const float4* a4p = (const float4*)(Ash + bb * K + k);
#pragma unroll
            for (int q = 0; q < 4; q++) {
                float4 a = a4p[q];
                acc[bb] = fmaf(a.x, w[q * 4 + 0], acc[bb]);
                acc[bb] = fmaf(a.y, w[q * 4 + 1], acc[bb]);
                acc[bb] = fmaf(a.z, w[q * 4 + 2], acc[bb]);
                acc[bb] = fmaf(a.w, w[q * 4 + 3], acc[bb]);
            }
        }
    }
#pragma unroll
    for (int bb = 0; bb < 8; bb++) red[tid * 8 + bb] = acc[bb];
    __syncthreads();
    if (tid < 32) {
        float bsv = bias[col];
#pragma unroll
        for (int bb = 0; bb < 8; bb++) {
            float v = bsv;
#pragma unroll
            for (int s = 0; s < 8; s++)
                v += red[(tid + s * 32) * 8 + bb];
            if (RELU) v = fmaxf(v, 0.f);
            Out[(size_t)bb * N + col] = v;
        }
    }
}

// ---------------- launch ----------------
extern "C" void kernel_launch(void* const* d_in, const int* in_sizes, int n_in,
                              void* d_out, int out_size) {
    const float* x    = (const float*)d_in[0];
    const int*   cats = (const int*)  d_in[1];
    const float* W1   = (const float*)d_in[2];
    const float* b1   = (const float*)d_in[3];
    const float* W2   = (const float*)d_in[4];
    const float* b2   = (const float*)d_in[5];
    const float* Wc1  = (const float*)d_in[6];
    const float* bc1  = (const float*)d_in[7];
    const float* Wc2  = (const float*)d_in[8];
    const float* bc2  = (const float*)d_in[9];
    const float* Wc3  = (const float*)d_in[10];
    const float* bc3  = (const float*)d_in[11];
    const float* Wd1  = (const float*)d_in[12];
    const float* bd1  = (const float*)d_in[13];
    const float* Wd2  = (const float*)d_in[14];
    const float* bd2  = (const float*)d_in[15];
    const float* Wd3  = (const float*)d_in[16];
    const float* bd3  = (const float*)d_in[17];
    float* out = (float*)d_out;

    const int GS2 = 3 * (64 * 80 + 10240);    // FR=2 stages
    const int GS4 = 3 * (128 * 80 + 10240);   // FR=4 stages

    cudaFuncSetAttribute(k_expert_mma, cudaFuncAttributeMaxDynamicSharedMemorySize, ESMEM);
    cudaFuncSetAttribute(mlp8<1, 1>, cudaFuncAttributeMaxDynamicSharedMemorySize, 65536);
    cudaFuncSetAttribute(mlp8<1, 0>, cudaFuncAttributeMaxDynamicSharedMemorySize, 65536);
    cudaFuncSetAttribute(mlp8<0, 0>, cudaFuncAttributeMaxDynamicSharedMemorySize, 65536);
    cudaFuncSetAttribute(gemm_mma<K0PAD, 1, 1, 2>, cudaFuncAttributeMaxDynamicSharedMemorySize, GS2);
    cudaFuncSetAttribute(gemm_mma<C1OUT, 1, 1, 4>, cudaFuncAttributeMaxDynamicSharedMemorySize, GS4);
    cudaFuncSetAttribute(gemm_mma<C2OUT, 0, 0, 4>, cudaFuncAttributeMaxDynamicSharedMemorySize, GS4);

    h16 *p_a0h, *p_a1h, *p_a2h, *p_w1h, *p_w2h, *p_w3h;
    float *p_d1, *p_d2;
    cudaGetSymbolAddress((void**)&p_a0h, g_a0hi);
    cudaGetSymbolAddress((void**)&p_a1h, g_a1hi);
    cudaGetSymbolAddress((void**)&p_a2h, g_a2hi);
    cudaGetSymbolAddress((void**)&p_w1h, g_w1hi);
    cudaGetSymbolAddress((void**)&p_w2h, g_w2hi);
    cudaGetSymbolAddress((void**)&p_w3h, g_w3hi);
    cudaGetSymbolAddress((void**)&p_d1,  g_d1);
    cudaGetSymbolAddress((void**)&p_d2,  g_d2);

    k_prep<<<PREP_NB, 256>>>(x, W1, W2, Wc1, Wc2, Wc3);
    k_build<<<1, 1024>>>(cats);
    k_expert_mma<<<MAXTILES, 256, ESMEM>>>(b1, b2);

    // conv stack: all hi-only; gemm1 FR=2, gemm2/3 FR=4; gemm3 fuses pool
    gemm_mma<K0PAD, 1, 1, 2><<<dim3(128, C1OUT / 128), 256, GS2>>>(
        p_a0h, p_w1h, bc1, p_a1h, C1OUT);
    gemm_mma<C1OUT, 1, 1, 4><<<dim3(64, C2OUT / 128), 256, GS4>>>(
        p_a1h, p_w2h, bc2, p_a2h, C2OUT);
    gemm_mma<C2OUT, 0, 0, 4><<<dim3(64, C3OUT / 128), 256, GS4>>>(
        p_a2h, p_w3h, bc3, (h16*)0, C3OUT);

    // decoder: mlp1 fuses the final pool reduction (POOL=1)
    int write_extra = (out_size >= 65536 + 8192) ? 1 : 0;
    mlp8<1, 1><<<DEC1 / 32, 256, 8 * DEC1 * 4>>>(
        (const float*)0, Wd1, bd1, p_d1, DEC1, DEC1, out + 65536, write_extra);
    mlp8<1, 0><<<DEC2 / 32, 256, 8 * DEC1 * 4>>>(
        p_d1, Wd2, bd2, p_d2, DEC1, DEC2, (float*)0, 0);
    mlp8<0, 0><<<DEC3 / 32, 256, 8 * DEC2 * 4>>>(
        p_d2, Wd3, bd3, out, DEC2, DEC3, (float*)0, 0);
}